// round 14
// baseline (speedup 1.0000x reference)
#include <cuda_runtime.h>
#include <cuda_bf16.h>
#include <cstdint>

#define HW 65536
#define CN 64
#define C2 128
#define NB 8
#define EPSV 1e-6f

__device__ unsigned short g_u[(size_t)NB*C2*HW];   // bf16 pw1 output, 134MB
__device__ unsigned short g_g[(size_t)NB*CN*HW];   // bf16 gated, 67MB
__device__ float g_x1[(size_t)NB*CN*HW];           // fp32 first residual, 134MB
__device__ float g_mean1[NB*CN], g_rstd1[NB*CN], g_pool[NB*CN], g_sum2[NB*CN], g_sumsq2[NB*CN];
__device__ float g_b1e[NB*C2], g_b3e[NB*C2];
__device__ __align__(16) unsigned g_w1p[NB*C2*32];
__device__ __align__(16) unsigned g_w2p[NB*CN*32];
__device__ __align__(16) unsigned g_w3p[NB*C2*32];
__device__ __align__(16) unsigned g_w4p[CN*32];

// res = {lo: a, hi: b}
#define CVT2(res,a,b) asm("cvt.rn.satfinite.bf16x2.f32 %0, %1, %2;" : "=r"(res) : "f"(b), "f"(a))
#define BF2F(u) __bfloat162float(__ushort_as_bfloat16(u))

__device__ __forceinline__ void mma16816(float* d, const unsigned* a, unsigned b0, unsigned b1) {
    asm volatile("mma.sync.aligned.m16n8k16.row.col.f32.bf16.bf16.f32 "
        "{%0,%1,%2,%3}, {%4,%5,%6,%7}, {%8,%9}, {%0,%1,%2,%3};"
        : "+f"(d[0]), "+f"(d[1]), "+f"(d[2]), "+f"(d[3])
        : "r"(a[0]), "r"(a[1]), "r"(a[2]), "r"(a[3]), "r"(b0), "r"(b1));
}

// k-word permutation: fragment pairs (ks*8+kp, ks*8+kp+4) become adjacent words
// so one LDS.64 fetches both halves of an A/B fragment.
__device__ __forceinline__ int newpos(int w) {
    int ks = w >> 3, r = w & 7;
    return (r < 4) ? 2 * (ks * 4 + r) : 2 * (ks * 4 + (r - 4)) + 1;
}

// stage 64-px fp32 ch-major -> bf16 [64px][36 words] (permuted), 512 threads
__device__ __forceinline__ void stage64_f32(unsigned* sa, const float* src, int n, int p0,
                                            int lane, int wid, int col) {
    const float4* xa = (const float4*)(src + ((size_t)(n * CN + 2 * lane)) * HW) + (p0 >> 2);
    const float4* xb = xa + (HW >> 2);
    float4 a = xa[wid], b = xb[wid];
    int p = wid * 4;
    unsigned v0, v1, v2, v3;
    CVT2(v0, a.x, b.x); CVT2(v1, a.y, b.y); CVT2(v2, a.z, b.z); CVT2(v3, a.w, b.w);
    sa[(p + 0) * 36 + col] = v0;
    sa[(p + 1) * 36 + col] = v1;
    sa[(p + 2) * 36 + col] = v2;
    sa[(p + 3) * 36 + col] = v3;
}

__device__ __forceinline__ void stage64_bf16(unsigned* sa, const unsigned short* src,
                                             int n, int p0, int lane, int wid, int col) {
    const ushort4* ga = (const ushort4*)(src + ((size_t)(n * CN + 2 * lane)) * HW + p0);
    const ushort4* gb = ga + (HW >> 2);
    ushort4 a = ga[wid], b = gb[wid];
    int p = wid * 4;
    sa[(p + 0) * 36 + col] = (unsigned)a.x | ((unsigned)b.x << 16);
    sa[(p + 1) * 36 + col] = (unsigned)a.y | ((unsigned)b.y << 16);
    sa[(p + 2) * 36 + col] = (unsigned)a.z | ((unsigned)b.z << 16);
    sa[(p + 3) * 36 + col] = (unsigned)a.w | ((unsigned)b.w << 16);
}

// 512-thread weight copy with permutation
__device__ __forceinline__ void copy_w(unsigned* sw, const unsigned* gw, int rows, int t) {
    int r = t >> 5, w = t & 31;
    int np = newpos(w);
    for (; r < rows; r += 16) sw[r * 36 + np] = gw[r * 32 + w];
}

template<int NT>
__device__ __forceinline__ void gemm_core(const unsigned* sw, const unsigned* sa,
                                          int ms, int ntb, int lane, float* d) {
    int r = ms + (lane >> 2), kp = lane & 3;
    #pragma unroll
    for (int ks = 0; ks < 4; ks++) {
        int kw = 2 * (ks * 4 + kp);
        uint2 aLo = *(const uint2*)&sw[r * 36 + kw];
        uint2 aHi = *(const uint2*)&sw[(r + 8) * 36 + kw];
        unsigned a[4] = { aLo.x, aHi.x, aLo.y, aHi.y };
        #pragma unroll
        for (int nt = 0; nt < NT; nt++) {
            int px = (ntb + nt) * 8 + (lane >> 2);
            uint2 b = *(const uint2*)&sa[px * 36 + kw];
            mma16816(d + nt * 4, a, b.x, b.y);
        }
    }
}

// ---------------- K1: LN1 stats ---------------------------------------------------
__global__ void __launch_bounds__(512) k_stats1(const float* __restrict__ x) {
    int nc = blockIdx.x;
    const float4* p = (const float4*)(x + (size_t)nc * HW);
    float s = 0.f, q = 0.f;
    for (int j = threadIdx.x; j < HW / 4; j += 512) {
        float4 v = p[j];
        s += v.x + v.y + v.z + v.w;
        q += v.x * v.x + v.y * v.y + v.z * v.z + v.w * v.w;
    }
    __shared__ float rs[16], rq[16];
    for (int o = 16; o; o >>= 1) {
        s += __shfl_down_sync(0xffffffffu, s, o);
        q += __shfl_down_sync(0xffffffffu, q, o);
    }
    if ((threadIdx.x & 31) == 0) { rs[threadIdx.x >> 5] = s; rq[threadIdx.x >> 5] = q; }
    __syncthreads();
    if (threadIdx.x == 0) {
        float S = 0.f, Q = 0.f;
        for (int i = 0; i < 16; i++) { S += rs[i]; Q += rq[i]; }
        float m = S * (1.f / HW);
        g_mean1[nc] = m;
        g_rstd1[nc] = rsqrtf(Q * (1.f / HW) - m * m + EPSV);
    }
}

// ---------------- K2: fold LN1 -> pw1 packed bf16 ---------------------------------
__global__ void k_prep1(const float* __restrict__ ln1w, const float* __restrict__ ln1b,
                        const float* __restrict__ pw1w, const float* __restrict__ pw1b) {
    int n = blockIdx.x, o = threadIdx.x;   // 128
    float bias = pw1b[o], row[CN];
    for (int i = 0; i < CN; i++) {
        float a  = g_rstd1[n * CN + i] * ln1w[i];
        float c0 = ln1b[i] - g_mean1[n * CN + i] * a;
        float w  = pw1w[o * CN + i];
        bias += w * c0;
        row[i] = w * a;
    }
    g_b1e[n * C2 + o] = bias;
    unsigned* dst = g_w1p + (n * C2 + o) * 32;
    for (int j = 0; j < 32; j++) { unsigned pk; CVT2(pk, row[2*j], row[2*j+1]); dst[j] = pk; }
    int idx = n * C2 + o;
    if (idx < NB * CN) { g_pool[idx] = 0.f; g_sum2[idx] = 0.f; g_sumsq2[idx] = 0.f; }
}

// ---------------- K3: pw1 mma GEMM (512 thr, 64px tiles, bf16 out) ----------------
__global__ void __launch_bounds__(512) k_pw1(const float* __restrict__ x) {
    __shared__ __align__(16) unsigned sw[C2 * 36];
    __shared__ __align__(16) unsigned sa[64 * 36];
    int t = threadIdx.x, wid = t >> 5, lane = t & 31;
    int n = blockIdx.y, p0 = blockIdx.x * 64;
    copy_w(sw, g_w1p + n * C2 * 32, C2, t);
    stage64_f32(sa, x, n, p0, lane, wid, newpos(lane));
    __syncthreads();
    float d[16];
    #pragma unroll
    for (int i = 0; i < 16; i++) d[i] = 0.f;
    gemm_core<4>(sw, sa, (wid & 7) * 16, (wid >> 3) * 4, lane, d);
    int o1 = (wid & 7) * 16 + (lane >> 2), o2 = o1 + 8;
    float bi1 = g_b1e[n * C2 + o1], bi2 = g_b1e[n * C2 + o2];
    unsigned short* u1 = g_u + (size_t)(n * C2 + o1) * HW + p0;
    unsigned short* u2 = g_u + (size_t)(n * C2 + o2) * HW + p0;
    #pragma unroll
    for (int nt = 0; nt < 4; nt++) {
        int px = (wid >> 3) * 32 + nt * 8 + (lane & 3) * 2;
        unsigned pk1, pk2;
        CVT2(pk1, d[nt*4+0] + bi1, d[nt*4+1] + bi1);
        CVT2(pk2, d[nt*4+2] + bi2, d[nt*4+3] + bi2);
        *(unsigned*)(u1 + px) = pk1;
        *(unsigned*)(u2 + px) = pk2;
    }
}

// ---------------- K4: depthwise 3x3 + gate + pool (register-tiled 4x4) ------------
__global__ void __launch_bounds__(256) k_dwgate(const float* __restrict__ dww,
                                                const float* __restrict__ dwb) {
    __shared__ float s[2][18][256];
    __shared__ float red[8];
    int t = threadIdx.x, tx = t & 63, ty = t >> 6;
    int nc = blockIdx.x, n = nc >> 6, c = nc & 63;
    int strip0 = blockIdx.y * 32;
    const unsigned short* u0 = g_u + ((size_t)(n * C2 + c)) * HW;
    const unsigned short* u1 = g_u + ((size_t)(n * C2 + c + 64)) * HW;
    unsigned short* gp = g_g + ((size_t)(n * CN + c)) * HW;
    float w0[9], w1[9];
    #pragma unroll
    for (int k = 0; k < 9; k++) { w0[k] = __ldg(dww + c * 9 + k); w1[k] = __ldg(dww + (c + 64) * 9 + k); }
    float b0 = __ldg(dwb + c), b1 = __ldg(dwb + c + 64);
    float psum = 0.f;
    #pragma unroll 1
    for (int it = 0; it < 2; it++) {
        int base = strip0 + it * 16;
        #pragma unroll
        for (int k = 0; k < 9; k++) {
            int idx = t + k * 256;
            int ch = (idx >= 1152);
            int rem = idx - ch * 1152;
            int lr = rem >> 6, c8 = rem & 63;
            int ar = base - 1 + lr;
            float4 f = make_float4(0.f, 0.f, 0.f, 0.f);
            if ((unsigned)ar < 256u) {
                ushort4 v = *(const ushort4*)((ch ? u1 : u0) + ar * 256 + c8 * 4);
                f = make_float4(BF2F(v.x), BF2F(v.y), BF2F(v.z), BF2F(v.w));
            }
            *(float4*)(&s[ch][lr][c8 * 4]) = f;
        }
        __syncthreads();
        float acc0[16], acc1[16];
        #pragma unroll
        for (int i = 0; i < 16; i++) { acc0[i] = b0; acc1[i] = b1; }
        #pragma unroll
        for (int ch = 0; ch < 2; ch++) {
            float* acc = ch ? acc1 : acc0;
            const float* w = ch ? w1 : w0;
            #pragma unroll
            for (int lr = 0; lr < 6; lr++) {
                const float* row = &s[ch][ty * 4 + lr][0];
                float4 cv = *(const float4*)(row + tx * 4);
                float i0 = tx ? row[tx * 4 - 1] : 0.f;
                float i5 = (tx != 63) ? row[tx * 4 + 4] : 0.f;
                float i1 = cv.x, i2 = cv.y, i3 = cv.z, i4 = cv.w;
                #pragma unroll
                for (int ky = 0; ky < 3; ky++) {
                    int q = lr - ky;
                    if (q >= 0 && q < 4) {
                        acc[q*4+0] += w[ky*3]*i0 + w[ky*3+1]*i1 + w[ky*3+2]*i2;
                        acc[q*4+1] += w[ky*3]*i1 + w[ky*3+1]*i2 + w[ky*3+2]*i3;
                        acc[q*4+2] += w[ky*3]*i2 + w[ky*3+1]*i3 + w[ky*3+2]*i4;
                        acc[q*4+3] += w[ky*3]*i3 + w[ky*3+1]*i4 + w[ky*3+2]*i5;
                    }
                }
            }
        }
        #pragma unroll
        for (int q = 0; q < 4; q++) {
            int r = base + ty * 4 + q;
            float g0 = acc0[q*4+0] * acc1[q*4+0];
            float g1 = acc0[q*4+1] * acc1[q*4+1];
            float g2 = acc0[q*4+2] * acc1[q*4+2];
            float g3 = acc0[q*4+3] * acc1[q*4+3];
            unsigned pk0, pk1;
            CVT2(pk0, g0, g1); CVT2(pk1, g2, g3);
            *(uint2*)(gp + r * 256 + tx * 4) = make_uint2(pk0, pk1);
            psum += (g0 + g1) + (g2 + g3);
        }
        __syncthreads();
    }
    for (int o = 16; o; o >>= 1) psum += __shfl_down_sync(0xffffffffu, psum, o);
    if ((t & 31) == 0) red[t >> 5] = psum;
    __syncthreads();
    if (t < 8) {
        float v = red[t];
        v += __shfl_down_sync(0xffu, v, 4);
        v += __shfl_down_sync(0xffu, v, 2);
        v += __shfl_down_sync(0xffu, v, 1);
        if (t == 0) atomicAdd(&g_pool[nc], v);
    }
}

// ---------------- K5: SCA -> pw2 packed bf16 --------------------------------------
__global__ void k_sca(const float* __restrict__ scaw, const float* __restrict__ scab,
                      const float* __restrict__ pw2w) {
    int n = blockIdx.x, o = threadIdx.x;   // 64
    __shared__ float pm[CN], sc[CN];
    pm[o] = g_pool[n * CN + o] * (1.f / HW);
    __syncthreads();
    float acc = scab[o];
    for (int i = 0; i < CN; i++) acc += scaw[o * CN + i] * pm[i];
    sc[o] = 1.f / (1.f + expf(-acc));
    __syncthreads();
    unsigned* dst = g_w2p + (n * CN + o) * 32;
    for (int j = 0; j < 32; j++) {
        unsigned pk;
        CVT2(pk, pw2w[o * CN + 2*j] * sc[2*j], pw2w[o * CN + 2*j+1] * sc[2*j+1]);
        dst[j] = pk;
    }
}

// ---------------- K6: pw2 mma GEMM + residual + LN2 stats (512 thr, 64px) ---------
__global__ void __launch_bounds__(512) k_pw2(const float* __restrict__ x,
                                             const float* __restrict__ pw2b,
                                             const float* __restrict__ beta1) {
    __shared__ __align__(16) unsigned sw[CN * 36];
    __shared__ __align__(16) unsigned sa[64 * 36];
    int t = threadIdx.x, wid = t >> 5, lane = t & 31;
    int n = blockIdx.y, p0 = blockIdx.x * 64;
    copy_w(sw, g_w2p + n * CN * 32, CN, t);
    stage64_bf16(sa, g_g, n, p0, lane, wid, newpos(lane));
    __syncthreads();
    float d[8];
    #pragma unroll
    for (int i = 0; i < 8; i++) d[i] = 0.f;
    gemm_core<2>(sw, sa, (wid & 3) * 16, (wid >> 2) * 2, lane, d);
    int o1 = (wid & 3) * 16 + (lane >> 2), o2 = o1 + 8;
    float b1 = pw2b[o1], b2 = pw2b[o2], t1 = beta1[o1], t2 = beta1[o2];
    size_t off1 = (size_t)(n * CN + o1) * HW + p0;
    size_t off2 = (size_t)(n * CN + o2) * HW + p0;
    float s1 = 0.f, q1 = 0.f, s2 = 0.f, q2 = 0.f;
    #pragma unroll
    for (int nt = 0; nt < 2; nt++) {
        int px = (wid >> 2) * 16 + nt * 8 + (lane & 3) * 2;
        float2 xv1 = *(const float2*)(x + off1 + px);
        float2 xv2 = *(const float2*)(x + off2 + px);
        float2 r1 = make_float2(xv1.x + t1 * (d[nt*4+0] + b1), xv1.y + t1 * (d[nt*4+1] + b1));
        float2 r2 = make_float2(xv2.x + t2 * (d[nt*4+2] + b2), xv2.y + t2 * (d[nt*4+3] + b2));
        *(float2*)(g_x1 + off1 + px) = r1;
        *(float2*)(g_x1 + off2 + px) = r2;
        s1 += r1.x + r1.y; q1 += r1.x * r1.x + r1.y * r1.y;
        s2 += r2.x + r2.y; q2 += r2.x * r2.x + r2.y * r2.y;
    }
    s1 += __shfl_xor_sync(~0u, s1, 1); s1 += __shfl_xor_sync(~0u, s1, 2);
    q1 += __shfl_xor_sync(~0u, q1, 1); q1 += __shfl_xor_sync(~0u, q1, 2);
    s2 += __shfl_xor_sync(~0u, s2, 1); s2 += __shfl_xor_sync(~0u, s2, 2);
    q2 += __shfl_xor_sync(~0u, q2, 1); q2 += __shfl_xor_sync(~0u, q2, 2);
    if ((lane & 3) == 0) {
        atomicAdd(&g_sum2[n * CN + o1], s1);
        atomicAdd(&g_sumsq2[n * CN + o1], q1);
        atomicAdd(&g_sum2[n * CN + o2], s2);
        atomicAdd(&g_sumsq2[n * CN + o2], q2);
    }
}

// ---------------- K7: LN2 -> pw3 packed; pw4 packed -------------------------------
__global__ void k_prep3(const float* __restrict__ ln2w, const float* __restrict__ ln2b,
                        const float* __restrict__ pw3w, const float* __restrict__ pw3b,
                        const float* __restrict__ pw4w) {
    int n = blockIdx.x, o = threadIdx.x;   // 128
    __shared__ float m2[CN], r2[CN];
    if (o < CN) {
        float m = g_sum2[n * CN + o] * (1.f / HW);
        m2[o] = m;
        r2[o] = rsqrtf(g_sumsq2[n * CN + o] * (1.f / HW) - m * m + EPSV);
    }
    __syncthreads();
    float bias = pw3b[o], row[CN];
    for (int i = 0; i < CN; i++) {
        float a  = r2[i] * ln2w[i];
        float c0 = ln2b[i] - m2[i] * a;
        float w  = pw3w[o * CN + i];
        bias += w * c0;
        row[i] = w * a;
    }
    g_b3e[n * C2 + o] = bias;
    unsigned* dst = g_w3p + (n * C2 + o) * 32;
    for (int j = 0; j < 32; j++) { unsigned pk; CVT2(pk, row[2*j], row[2*j+1]); dst[j] = pk; }
    if (n == 0 && o < CN) {
        unsigned* d4 = g_w4p + o * 32;
        for (int j = 0; j < 32; j++) {
            unsigned pk; CVT2(pk, pw4w[o * CN + 2*j], pw4w[o * CN + 2*j+1]);
            d4[j] = pk;
        }
    }
}

// ---------------- K8: pw3 MMA -> gate -> pw4 MMA -> residual -> out (64px) --------
__global__ void __launch_bounds__(512) k_final(const float* __restrict__ pw4b,
                                               const float* __restrict__ beta2,
                                               float* __restrict__ out) {
    extern __shared__ __align__(16) char smem[];
    float*    x1s  = (float*)smem;                      // [64][66] fp32 = 16896
    unsigned* w3   = (unsigned*)(smem + 16896);         // 18432
    unsigned* w4   = (unsigned*)(smem + 16896 + 18432); // 9216
    unsigned* bufB = (unsigned*)(smem + 44544);         // 9216 (B3 then B4)
    unsigned short* sc2 = (unsigned short*)w3;          // overlay after pw3 (9216 used)
    int t = threadIdx.x, wid = t >> 5, lane = t & 31;
    int n = blockIdx.y, p0 = blockIdx.x * 64;
    copy_w(w3, g_w3p + n * C2 * 32, C2, t);
    copy_w(w4, g_w4p, CN, t);
    {
        const float4* xa = (const float4*)(g_x1 + ((size_t)(n * CN + 2 * lane)) * HW) + (p0 >> 2);
        const float4* xb = xa + (HW >> 2);
        float2* x1s2 = (float2*)x1s;
        float4 a = xa[wid], b = xb[wid];
        int p = wid * 4;
        x1s2[(p + 0) * 33 + lane] = make_float2(a.x, b.x);
        x1s2[(p + 1) * 33 + lane] = make_float2(a.y, b.y);
        x1s2[(p + 2) * 33 + lane] = make_float2(a.z, b.z);
        x1s2[(p + 3) * 33 + lane] = make_float2(a.w, b.w);
        int col = newpos(lane);
        unsigned v0, v1, v2, v3;
        CVT2(v0, a.x, b.x); CVT2(v1, a.y, b.y); CVT2(v2, a.z, b.z); CVT2(v3, a.w, b.w);
        bufB[(p + 0) * 36 + col] = v0;
        bufB[(p + 1) * 36 + col] = v1;
        bufB[(p + 2) * 36 + col] = v2;
        bufB[(p + 3) * 36 + col] = v3;
    }
    __syncthreads();
    float d[16];
    #pragma unroll
    for (int i = 0; i < 16; i++) d[i] = 0.f;
    gemm_core<4>(w3, bufB, (wid & 7) * 16, (wid >> 3) * 4, lane, d);
    int r1 = (wid & 7) * 16 + (lane >> 2), r2 = r1 + 8;
    int pgrp = (wid >> 3) * 32;
    float b31 = g_b3e[n * C2 + r1], b32 = g_b3e[n * C2 + r2];
    __syncthreads();   // all warps done reading w3/bufB
    if ((wid & 7) >= 4) {   // hi strips: write y_hi bf16 into sc2 [px][72]
        int c1 = r1 - 64, c2 = r2 - 64;
        #pragma unroll
        for (int nt = 0; nt < 4; nt++) {
            int px = pgrp + nt * 8 + (lane & 3) * 2;
            sc2[px * 72 + c1]       = __bfloat16_as_ushort(__float2bfloat16_rn(d[nt*4+0] + b31));
            sc2[(px + 1) * 72 + c1] = __bfloat16_as_ushort(__float2bfloat16_rn(d[nt*4+1] + b31));
            sc2[px * 72 + c2]       = __bfloat16_as_ushort(__float2bfloat16_rn(d[nt*4+2] + b32));
            sc2[(px + 1) * 72 + c2] = __bfloat16_as_ushort(__float2bfloat16_rn(d[nt*4+3] + b32));
        }
    }
    __syncthreads();
    if ((wid & 7) < 4) {    // lo strips: gate, write B4 bf16 into bufB (permuted cols)
        unsigned short* b4s = (unsigned short*)bufB;
        int col1 = newpos(r1 >> 1) * 2 + (r1 & 1);
        int col2 = newpos(r2 >> 1) * 2 + (r2 & 1);
        #pragma unroll
        for (int nt = 0; nt < 4; nt++) {
            int px = pgrp + nt * 8 + (lane & 3) * 2;
            float h0 = BF2F(sc2[px * 72 + r1]);
            float h1 = BF2F(sc2[(px + 1) * 72 + r1]);
            float h2 = BF2F(sc2[px * 72 + r2]);
            float h3 = BF2F(sc2[(px + 1) * 72 + r2]);
            b4s[px * 72 + col1]       = __bfloat16_as_ushort(__float2bfloat16_rn((d[nt*4+0] + b31) * h0));
            b4s[(px + 1) * 72 + col1] = __bfloat16_as_ushort(__float2bfloat16_rn((d[nt*4+1] + b31) * h1));
            b4s[px * 72 + col2]       = __bfloat16_as_ushort(__float2bfloat16_rn((d[nt*4+2] + b32) * h2));
            b4s[(px + 1) * 72 + col2] = __bfloat16_as_ushort(__float2bfloat16_rn((d[nt*4+3] + b32) * h3));
        }
    }
    __syncthreads();
    float e[8];
    #pragma unroll
    for (int i = 0; i < 8; i++) e[i] = 0.f;
    gemm_core<2>(w4, bufB, (wid & 3) * 16, (wid >> 2) * 2, lane, e);
    int o1 = (wid & 3) * 16 + (lane >> 2), o2 = o1 + 8;
    float b41 = pw4b[o1], b42 = pw4b[o2], t41 = beta2[o1], t42 = beta2[o2];
    float* op1 = out + (size_t)(n * CN + o1) * HW + p0;
    float* op2 = out + (size_t)(n * CN + o2) * HW + p0;
    #pragma unroll
    for (int nt = 0; nt < 2; nt++) {
        int px = (wid >> 2) * 16 + nt * 8 + (lane & 3) * 2;
        float2 r1v, r2v;
        r1v.x = x1s[px * 66 + o1]       + t41 * (e[nt*4+0] + b41);
        r1v.y = x1s[(px + 1) * 66 + o1] + t41 * (e[nt*4+1] + b41);
        r2v.x = x1s[px * 66 + o2]       + t42 * (e[nt*4+2] + b42);
        r2v.y = x1s[(px + 1) * 66 + o2] + t42 * (e[nt*4+3] + b42);
        *(float2*)(op1 + px) = r1v;
        *(float2*)(op2 + px) = r2v;
    }
}

// ---------------- host ------------------------------------------------------------
extern "C" void kernel_launch(void* const* d_in, const int* in_sizes, int n_in,
                              void* d_out, int out_size) {
    const float* x     = (const float*)d_in[0];
    const float* ln1w  = (const float*)d_in[1];
    const float* ln1b  = (const float*)d_in[2];
    const float* pw1w  = (const float*)d_in[3];
    const float* pw1b  = (const float*)d_in[4];
    const float* dww   = (const float*)d_in[5];
    const float* dwb   = (const float*)d_in[6];
    const float* scaw  = (const float*)d_in[7];
    const float* scab  = (const float*)d_in[8];
    const float* pw2w  = (const float*)d_in[9];
    const float* pw2b  = (const float*)d_in[10];
    const float* ln2w  = (const float*)d_in[11];
    const float* ln2b  = (const float*)d_in[12];
    const float* pw3w  = (const float*)d_in[13];
    const float* pw3b  = (const float*)d_in[14];
    const float* pw4w  = (const float*)d_in[15];
    const float* pw4b  = (const float*)d_in[16];
    const float* beta1 = (const float*)d_in[17];
    const float* beta2 = (const float*)d_in[18];

    cudaFuncSetAttribute(k_final, cudaFuncAttributeMaxDynamicSharedMemorySize, 56 * 1024);

    k_stats1<<<NB * CN, 512>>>(x);
    k_prep1<<<NB, C2>>>(ln1w, ln1b, pw1w, pw1b);
    k_pw1<<<dim3(1024, NB), 512>>>(x);
    k_dwgate<<<dim3(NB * CN, 8), 256>>>(dww, dwb);
    k_sca<<<NB, CN>>>(scaw, scab, pw2w);
    k_pw2<<<dim3(1024, NB), 512>>>(x, pw2b, beta1);
    k_prep3<<<NB, C2>>>(ln2w, ln2b, pw3w, pw3b, pw4w);
    k_final<<<dim3(1024, NB), 512, 56 * 1024>>>(pw4b, beta2, (float*)d_out);
}

// round 15
// speedup vs baseline: 1.1886x; 1.1886x over previous
#include <cuda_runtime.h>
#include <cuda_bf16.h>
#include <cstdint>

#define HW 65536
#define CN 64
#define C2 128
#define NB 8
#define EPSV 1e-6f

__device__ unsigned short g_u[(size_t)NB*C2*HW];   // bf16 pw1 output, 134MB
__device__ unsigned short g_g[(size_t)NB*CN*HW];   // bf16 gated, 67MB
__device__ float g_x1[(size_t)NB*CN*HW];           // fp32 first residual, 134MB
__device__ float g_mean1[NB*CN], g_rstd1[NB*CN], g_pool[NB*CN], g_sum2[NB*CN], g_sumsq2[NB*CN];
__device__ float g_b1e[NB*C2], g_b3e[NB*C2];
__device__ __align__(16) unsigned g_w1p[NB*C2*32];
__device__ __align__(16) unsigned g_w2p[NB*CN*32];
__device__ __align__(16) unsigned g_w3p[NB*C2*32];
__device__ __align__(16) unsigned g_w4p[CN*32];

// res = {lo: a, hi: b}
#define CVT2(res,a,b) asm("cvt.rn.satfinite.bf16x2.f32 %0, %1, %2;" : "=r"(res) : "f"(b), "f"(a))
#define BF2F(u) __bfloat162float(__ushort_as_bfloat16(u))

__device__ __forceinline__ void mma16816(float* d, const unsigned* a, unsigned b0, unsigned b1) {
    asm volatile("mma.sync.aligned.m16n8k16.row.col.f32.bf16.bf16.f32 "
        "{%0,%1,%2,%3}, {%4,%5,%6,%7}, {%8,%9}, {%0,%1,%2,%3};"
        : "+f"(d[0]), "+f"(d[1]), "+f"(d[2]), "+f"(d[3])
        : "r"(a[0]), "r"(a[1]), "r"(a[2]), "r"(a[3]), "r"(b0), "r"(b1));
}

// k-word permutation: fragment pair (ks*8+kp, ks*8+kp+4) -> adjacent words,
// so one LDS.64 fetches both halves of an A/B fragment.
__device__ __forceinline__ int newpos(int w) {
    int ks = w >> 3, r = w & 7;
    return (r < 4) ? 2 * (ks * 4 + r) : 2 * (ks * 4 + (r - 4)) + 1;
}

// 512-thread staging: fp32 ch-major -> bf16 [128px][36 words] (permuted cols)
__device__ __forceinline__ void stage_acts_f32(unsigned* sa, const float* src, int n, int p0,
                                               int lane, int wid, int col) {
    const float4* xa = (const float4*)(src + ((size_t)(n * CN + 2 * lane)) * HW) + (p0 >> 2);
    const float4* xb = xa + (HW >> 2);
    #pragma unroll
    for (int j = 0; j < 2; j++) {
        int px4 = wid * 2 + j;
        float4 a = xa[px4], b = xb[px4];
        int p = px4 * 4;
        unsigned v0, v1, v2, v3;
        CVT2(v0, a.x, b.x); CVT2(v1, a.y, b.y); CVT2(v2, a.z, b.z); CVT2(v3, a.w, b.w);
        sa[(p + 0) * 36 + col] = v0;
        sa[(p + 1) * 36 + col] = v1;
        sa[(p + 2) * 36 + col] = v2;
        sa[(p + 3) * 36 + col] = v3;
    }
}

__device__ __forceinline__ void stage_acts_bf16(unsigned* sa, const unsigned short* src,
                                                int n, int p0, int lane, int wid, int col) {
    const ushort4* ga = (const ushort4*)(src + ((size_t)(n * CN + 2 * lane)) * HW + p0);
    const ushort4* gb = ga + (HW >> 2);
    #pragma unroll
    for (int j = 0; j < 2; j++) {
        int px4 = wid * 2 + j;
        ushort4 a = ga[px4], b = gb[px4];
        int p = px4 * 4;
        sa[(p + 0) * 36 + col] = (unsigned)a.x | ((unsigned)b.x << 16);
        sa[(p + 1) * 36 + col] = (unsigned)a.y | ((unsigned)b.y << 16);
        sa[(p + 2) * 36 + col] = (unsigned)a.z | ((unsigned)b.z << 16);
        sa[(p + 3) * 36 + col] = (unsigned)a.w | ((unsigned)b.w << 16);
    }
}

// 512-thread weight copy with permutation
__device__ __forceinline__ void copy_w(unsigned* sw, const unsigned* gw, int rows, int t) {
    int r = t >> 5, w = t & 31;
    int np = newpos(w);
    for (; r < rows; r += 16) sw[r * 36 + np] = gw[r * 32 + w];
}

template<int NT>
__device__ __forceinline__ void gemm_core(const unsigned* sw, const unsigned* sa,
                                          int ms, int ntb, int lane, float* d) {
    int r = ms + (lane >> 2), kp = lane & 3;
    #pragma unroll
    for (int ks = 0; ks < 4; ks++) {
        int kw = 2 * (ks * 4 + kp);
        uint2 aLo = *(const uint2*)&sw[r * 36 + kw];
        uint2 aHi = *(const uint2*)&sw[(r + 8) * 36 + kw];
        unsigned a[4] = { aLo.x, aHi.x, aLo.y, aHi.y };
        #pragma unroll
        for (int nt = 0; nt < NT; nt++) {
            int px = (ntb + nt) * 8 + (lane >> 2);
            uint2 b = *(const uint2*)&sa[px * 36 + kw];
            mma16816(d + nt * 4, a, b.x, b.y);
        }
    }
}

// ---------------- K1: LN1 stats ---------------------------------------------------
__global__ void __launch_bounds__(512) k_stats1(const float* __restrict__ x) {
    int nc = blockIdx.x;
    const float4* p = (const float4*)(x + (size_t)nc * HW);
    float s = 0.f, q = 0.f;
    for (int j = threadIdx.x; j < HW / 4; j += 512) {
        float4 v = p[j];
        s += v.x + v.y + v.z + v.w;
        q += v.x * v.x + v.y * v.y + v.z * v.z + v.w * v.w;
    }
    __shared__ float rs[16], rq[16];
    for (int o = 16; o; o >>= 1) {
        s += __shfl_down_sync(0xffffffffu, s, o);
        q += __shfl_down_sync(0xffffffffu, q, o);
    }
    if ((threadIdx.x & 31) == 0) { rs[threadIdx.x >> 5] = s; rq[threadIdx.x >> 5] = q; }
    __syncthreads();
    if (threadIdx.x == 0) {
        float S = 0.f, Q = 0.f;
        for (int i = 0; i < 16; i++) { S += rs[i]; Q += rq[i]; }
        float m = S * (1.f / HW);
        g_mean1[nc] = m;
        g_rstd1[nc] = rsqrtf(Q * (1.f / HW) - m * m + EPSV);
    }
}

// ---------------- K2: fold LN1 -> pw1 packed bf16 ---------------------------------
__global__ void k_prep1(const float* __restrict__ ln1w, const float* __restrict__ ln1b,
                        const float* __restrict__ pw1w, const float* __restrict__ pw1b) {
    int n = blockIdx.x, o = threadIdx.x;   // 128
    float bias = pw1b[o], row[CN];
    for (int i = 0; i < CN; i++) {
        float a  = g_rstd1[n * CN + i] * ln1w[i];
        float c0 = ln1b[i] - g_mean1[n * CN + i] * a;
        float w  = pw1w[o * CN + i];
        bias += w * c0;
        row[i] = w * a;
    }
    g_b1e[n * C2 + o] = bias;
    unsigned* dst = g_w1p + (n * C2 + o) * 32;
    for (int j = 0; j < 32; j++) { unsigned pk; CVT2(pk, row[2*j], row[2*j+1]); dst[j] = pk; }
    int idx = n * C2 + o;
    if (idx < NB * CN) { g_pool[idx] = 0.f; g_sum2[idx] = 0.f; g_sumsq2[idx] = 0.f; }
}

// ---------------- K3: pw1 mma GEMM (512 thr, 128px, bf16 out) ---------------------
__global__ void __launch_bounds__(512) k_pw1(const float* __restrict__ x) {
    __shared__ __align__(16) unsigned sw[C2 * 36];
    __shared__ __align__(16) unsigned sa[128 * 36];
    int t = threadIdx.x, wid = t >> 5, lane = t & 31;
    int n = blockIdx.y, p0 = blockIdx.x * 128;
    copy_w(sw, g_w1p + n * C2 * 32, C2, t);
    stage_acts_f32(sa, x, n, p0, lane, wid, newpos(lane));
    __syncthreads();
    float d[32];
    #pragma unroll
    for (int i = 0; i < 32; i++) d[i] = 0.f;
    gemm_core<8>(sw, sa, (wid & 7) * 16, (wid >> 3) * 8, lane, d);
    int o1 = (wid & 7) * 16 + (lane >> 2), o2 = o1 + 8;
    float bi1 = g_b1e[n * C2 + o1], bi2 = g_b1e[n * C2 + o2];
    unsigned short* u1 = g_u + (size_t)(n * C2 + o1) * HW + p0;
    unsigned short* u2 = g_u + (size_t)(n * C2 + o2) * HW + p0;
    #pragma unroll
    for (int nt = 0; nt < 8; nt++) {
        int px = (wid >> 3) * 64 + nt * 8 + (lane & 3) * 2;
        unsigned pk1, pk2;
        CVT2(pk1, d[nt*4+0] + bi1, d[nt*4+1] + bi1);
        CVT2(pk2, d[nt*4+2] + bi2, d[nt*4+3] + bi2);
        *(unsigned*)(u1 + px) = pk1;
        *(unsigned*)(u2 + px) = pk2;
    }
}

// ---------------- K4: depthwise 3x3 + gate + pool (register-tiled 4x4) ------------
__global__ void __launch_bounds__(256) k_dwgate(const float* __restrict__ dww,
                                                const float* __restrict__ dwb) {
    __shared__ float s[2][18][256];
    __shared__ float red[8];
    int t = threadIdx.x, tx = t & 63, ty = t >> 6;
    int nc = blockIdx.x, n = nc >> 6, c = nc & 63;
    int strip0 = blockIdx.y * 32;
    const unsigned short* u0 = g_u + ((size_t)(n * C2 + c)) * HW;
    const unsigned short* u1 = g_u + ((size_t)(n * C2 + c + 64)) * HW;
    unsigned short* gp = g_g + ((size_t)(n * CN + c)) * HW;
    float w0[9], w1[9];
    #pragma unroll
    for (int k = 0; k < 9; k++) { w0[k] = __ldg(dww + c * 9 + k); w1[k] = __ldg(dww + (c + 64) * 9 + k); }
    float b0 = __ldg(dwb + c), b1 = __ldg(dwb + c + 64);
    float psum = 0.f;
    #pragma unroll 1
    for (int it = 0; it < 2; it++) {
        int base = strip0 + it * 16;
        #pragma unroll
        for (int k = 0; k < 9; k++) {
            int idx = t + k * 256;
            int ch = (idx >= 1152);
            int rem = idx - ch * 1152;
            int lr = rem >> 6, c8 = rem & 63;
            int ar = base - 1 + lr;
            float4 f = make_float4(0.f, 0.f, 0.f, 0.f);
            if ((unsigned)ar < 256u) {
                ushort4 v = *(const ushort4*)((ch ? u1 : u0) + ar * 256 + c8 * 4);
                f = make_float4(BF2F(v.x), BF2F(v.y), BF2F(v.z), BF2F(v.w));
            }
            *(float4*)(&s[ch][lr][c8 * 4]) = f;
        }
        __syncthreads();
        float acc0[16], acc1[16];
        #pragma unroll
        for (int i = 0; i < 16; i++) { acc0[i] = b0; acc1[i] = b1; }
        #pragma unroll
        for (int ch = 0; ch < 2; ch++) {
            float* acc = ch ? acc1 : acc0;
            const float* w = ch ? w1 : w0;
            #pragma unroll
            for (int lr = 0; lr < 6; lr++) {
                const float* row = &s[ch][ty * 4 + lr][0];
                float4 cv = *(const float4*)(row + tx * 4);
                float i0 = tx ? row[tx * 4 - 1] : 0.f;
                float i5 = (tx != 63) ? row[tx * 4 + 4] : 0.f;
                float i1 = cv.x, i2 = cv.y, i3 = cv.z, i4 = cv.w;
                #pragma unroll
                for (int ky = 0; ky < 3; ky++) {
                    int q = lr - ky;
                    if (q >= 0 && q < 4) {
                        acc[q*4+0] += w[ky*3]*i0 + w[ky*3+1]*i1 + w[ky*3+2]*i2;
                        acc[q*4+1] += w[ky*3]*i1 + w[ky*3+1]*i2 + w[ky*3+2]*i3;
                        acc[q*4+2] += w[ky*3]*i2 + w[ky*3+1]*i3 + w[ky*3+2]*i4;
                        acc[q*4+3] += w[ky*3]*i3 + w[ky*3+1]*i4 + w[ky*3+2]*i5;
                    }
                }
            }
        }
        #pragma unroll
        for (int q = 0; q < 4; q++) {
            int r = base + ty * 4 + q;
            float g0 = acc0[q*4+0] * acc1[q*4+0];
            float g1 = acc0[q*4+1] * acc1[q*4+1];
            float g2 = acc0[q*4+2] * acc1[q*4+2];
            float g3 = acc0[q*4+3] * acc1[q*4+3];
            unsigned pk0, pk1;
            CVT2(pk0, g0, g1); CVT2(pk1, g2, g3);
            *(uint2*)(gp + r * 256 + tx * 4) = make_uint2(pk0, pk1);
            psum += (g0 + g1) + (g2 + g3);
        }
        __syncthreads();
    }
    for (int o = 16; o; o >>= 1) psum += __shfl_down_sync(0xffffffffu, psum, o);
    if ((t & 31) == 0) red[t >> 5] = psum;
    __syncthreads();
    if (t < 8) {
        float v = red[t];
        v += __shfl_down_sync(0xffu, v, 4);
        v += __shfl_down_sync(0xffu, v, 2);
        v += __shfl_down_sync(0xffu, v, 1);
        if (t == 0) atomicAdd(&g_pool[nc], v);
    }
}

// ---------------- K5: SCA -> pw2 packed bf16 --------------------------------------
__global__ void k_sca(const float* __restrict__ scaw, const float* __restrict__ scab,
                      const float* __restrict__ pw2w) {
    int n = blockIdx.x, o = threadIdx.x;   // 64
    __shared__ float pm[CN], sc[CN];
    pm[o] = g_pool[n * CN + o] * (1.f / HW);
    __syncthreads();
    float acc = scab[o];
    for (int i = 0; i < CN; i++) acc += scaw[o * CN + i] * pm[i];
    sc[o] = 1.f / (1.f + expf(-acc));
    __syncthreads();
    unsigned* dst = g_w2p + (n * CN + o) * 32;
    for (int j = 0; j < 32; j++) {
        unsigned pk;
        CVT2(pk, pw2w[o * CN + 2*j] * sc[2*j], pw2w[o * CN + 2*j+1] * sc[2*j+1]);
        dst[j] = pk;
    }
}

// ---------------- K6: pw2 mma GEMM + residual + LN2 stats (512 thr, 128px) --------
__global__ void __launch_bounds__(512) k_pw2(const float* __restrict__ x,
                                             const float* __restrict__ pw2b,
                                             const float* __restrict__ beta1) {
    __shared__ __align__(16) unsigned sw[CN * 36];
    __shared__ __align__(16) unsigned sa[128 * 36];
    int t = threadIdx.x, wid = t >> 5, lane = t & 31;
    int n = blockIdx.y, p0 = blockIdx.x * 128;
    copy_w(sw, g_w2p + n * CN * 32, CN, t);
    stage_acts_bf16(sa, g_g, n, p0, lane, wid, newpos(lane));
    __syncthreads();
    float d[16];
    #pragma unroll
    for (int i = 0; i < 16; i++) d[i] = 0.f;
    gemm_core<4>(sw, sa, (wid & 3) * 16, (wid >> 2) * 4, lane, d);
    int o1 = (wid & 3) * 16 + (lane >> 2), o2 = o1 + 8;
    float b1 = pw2b[o1], b2 = pw2b[o2], t1 = beta1[o1], t2 = beta1[o2];
    size_t off1 = (size_t)(n * CN + o1) * HW + p0;
    size_t off2 = (size_t)(n * CN + o2) * HW + p0;
    float s1 = 0.f, q1 = 0.f, s2 = 0.f, q2 = 0.f;
    #pragma unroll
    for (int nt = 0; nt < 4; nt++) {
        int px = (wid >> 2) * 32 + nt * 8 + (lane & 3) * 2;
        float2 xv1 = *(const float2*)(x + off1 + px);
        float2 xv2 = *(const float2*)(x + off2 + px);
        float2 r1 = make_float2(xv1.x + t1 * (d[nt*4+0] + b1), xv1.y + t1 * (d[nt*4+1] + b1));
        float2 r2 = make_float2(xv2.x + t2 * (d[nt*4+2] + b2), xv2.y + t2 * (d[nt*4+3] + b2));
        *(float2*)(g_x1 + off1 + px) = r1;
        *(float2*)(g_x1 + off2 + px) = r2;
        s1 += r1.x + r1.y; q1 += r1.x * r1.x + r1.y * r1.y;
        s2 += r2.x + r2.y; q2 += r2.x * r2.x + r2.y * r2.y;
    }
    s1 += __shfl_xor_sync(~0u, s1, 1); s1 += __shfl_xor_sync(~0u, s1, 2);
    q1 += __shfl_xor_sync(~0u, q1, 1); q1 += __shfl_xor_sync(~0u, q1, 2);
    s2 += __shfl_xor_sync(~0u, s2, 1); s2 += __shfl_xor_sync(~0u, s2, 2);
    q2 += __shfl_xor_sync(~0u, q2, 1); q2 += __shfl_xor_sync(~0u, q2, 2);
    if ((lane & 3) == 0) {
        atomicAdd(&g_sum2[n * CN + o1], s1);
        atomicAdd(&g_sumsq2[n * CN + o1], q1);
        atomicAdd(&g_sum2[n * CN + o2], s2);
        atomicAdd(&g_sumsq2[n * CN + o2], q2);
    }
}

// ---------------- K7: LN2 -> pw3 packed; pw4 packed -------------------------------
__global__ void k_prep3(const float* __restrict__ ln2w, const float* __restrict__ ln2b,
                        const float* __restrict__ pw3w, const float* __restrict__ pw3b,
                        const float* __restrict__ pw4w) {
    int n = blockIdx.x, o = threadIdx.x;   // 128
    __shared__ float m2[CN], r2[CN];
    if (o < CN) {
        float m = g_sum2[n * CN + o] * (1.f / HW);
        m2[o] = m;
        r2[o] = rsqrtf(g_sumsq2[n * CN + o] * (1.f / HW) - m * m + EPSV);
    }
    __syncthreads();
    float bias = pw3b[o], row[CN];
    for (int i = 0; i < CN; i++) {
        float a  = r2[i] * ln2w[i];
        float c0 = ln2b[i] - m2[i] * a;
        float w  = pw3w[o * CN + i];
        bias += w * c0;
        row[i] = w * a;
    }
    g_b3e[n * C2 + o] = bias;
    unsigned* dst = g_w3p + (n * C2 + o) * 32;
    for (int j = 0; j < 32; j++) { unsigned pk; CVT2(pk, row[2*j], row[2*j+1]); dst[j] = pk; }
    if (n == 0 && o < CN) {
        unsigned* d4 = g_w4p + o * 32;
        for (int j = 0; j < 32; j++) {
            unsigned pk; CVT2(pk, pw4w[o * CN + 2*j], pw4w[o * CN + 2*j+1]);
            d4[j] = pk;
        }
    }
}

// ---------------- K8: pw3 MMA -> gate -> pw4 MMA -> residual -> out (128px) -------
__global__ void __launch_bounds__(512) k_final(const float* __restrict__ pw4b,
                                               const float* __restrict__ beta2,
                                               float* __restrict__ out) {
    extern __shared__ __align__(16) char smem[];
    float*    x1s  = (float*)smem;                              // [128][66] fp32 = 33792
    unsigned* w3   = (unsigned*)(smem + 33792);                 // 18432
    unsigned* w4   = (unsigned*)(smem + 33792 + 18432);         // 9216
    unsigned* bufB = (unsigned*)(smem + 33792 + 18432 + 9216);  // 18432 (B3 then B4)
    unsigned short* sc2 = (unsigned short*)w3;                  // overlay after pw3
    int t = threadIdx.x, wid = t >> 5, lane = t & 31;
    int n = blockIdx.y, p0 = blockIdx.x * 128;
    copy_w(w3, g_w3p + n * C2 * 32, C2, t);
    copy_w(w4, g_w4p, CN, t);
    {
        const float4* xa = (const float4*)(g_x1 + ((size_t)(n * CN + 2 * lane)) * HW) + (p0 >> 2);
        const float4* xb = xa + (HW >> 2);
        float2* x1s2 = (float2*)x1s;
        int col = newpos(lane);
        #pragma unroll
        for (int j = 0; j < 2; j++) {
            int px4 = wid * 2 + j;
            float4 a = xa[px4], b = xb[px4];
            int p = px4 * 4;
            x1s2[(p + 0) * 33 + lane] = make_float2(a.x, b.x);
            x1s2[(p + 1) * 33 + lane] = make_float2(a.y, b.y);
            x1s2[(p + 2) * 33 + lane] = make_float2(a.z, b.z);
            x1s2[(p + 3) * 33 + lane] = make_float2(a.w, b.w);
            unsigned v0, v1, v2, v3;
            CVT2(v0, a.x, b.x); CVT2(v1, a.y, b.y); CVT2(v2, a.z, b.z); CVT2(v3, a.w, b.w);
            bufB[(p + 0) * 36 + col] = v0;
            bufB[(p + 1) * 36 + col] = v1;
            bufB[(p + 2) * 36 + col] = v2;
            bufB[(p + 3) * 36 + col] = v3;
        }
    }
    __syncthreads();
    float d[32];
    #pragma unroll
    for (int i = 0; i < 32; i++) d[i] = 0.f;
    gemm_core<8>(w3, bufB, (wid & 7) * 16, (wid >> 3) * 8, lane, d);
    int r1 = (wid & 7) * 16 + (lane >> 2), r2 = r1 + 8;
    int pgrp = (wid >> 3) * 64;
    float b31 = g_b3e[n * C2 + r1], b32 = g_b3e[n * C2 + r2];
    __syncthreads();   // all warps done reading w3/bufB
    if ((wid & 7) >= 4) {   // hi strips: write y_hi bf16 into sc2 [px][72]
        int c1 = r1 - 64, c2 = r2 - 64;
        #pragma unroll
        for (int nt = 0; nt < 8; nt++) {
            int px = pgrp + nt * 8 + (lane & 3) * 2;
            sc2[px * 72 + c1]       = __bfloat16_as_ushort(__float2bfloat16_rn(d[nt*4+0] + b31));
            sc2[(px + 1) * 72 + c1] = __bfloat16_as_ushort(__float2bfloat16_rn(d[nt*4+1] + b31));
            sc2[px * 72 + c2]       = __bfloat16_as_ushort(__float2bfloat16_rn(d[nt*4+2] + b32));
            sc2[(px + 1) * 72 + c2] = __bfloat16_as_ushort(__float2bfloat16_rn(d[nt*4+3] + b32));
        }
    }
    __syncthreads();
    if ((wid & 7) < 4) {    // lo strips: gate, write B4 bf16 into bufB (permuted cols)
        unsigned short* b4s = (unsigned short*)bufB;
        int col1 = newpos(r1 >> 1) * 2 + (r1 & 1);
        int col2 = newpos(r2 >> 1) * 2 + (r2 & 1);
        #pragma unroll
        for (int nt = 0; nt < 8; nt++) {
            int px = pgrp + nt * 8 + (lane & 3) * 2;
            float h0 = BF2F(sc2[px * 72 + r1]);
            float h1 = BF2F(sc2[(px + 1) * 72 + r1]);
            float h2 = BF2F(sc2[px * 72 + r2]);
            float h3 = BF2F(sc2[(px + 1) * 72 + r2]);
            b4s[px * 72 + col1]       = __bfloat16_as_ushort(__float2bfloat16_rn((d[nt*4+0] + b31) * h0));
            b4s[(px + 1) * 72 + col1] = __bfloat16_as_ushort(__float2bfloat16_rn((d[nt*4+1] + b31) * h1));
            b4s[px * 72 + col2]       = __bfloat16_as_ushort(__float2bfloat16_rn((d[nt*4+2] + b32) * h2));
            b4s[(px + 1) * 72 + col2] = __bfloat16_as_ushort(__float2bfloat16_rn((d[nt*4+3] + b32) * h3));
        }
    }
    __syncthreads();
    float e[16];
    #pragma unroll
    for (int i = 0; i < 16; i++) e[i] = 0.f;
    gemm_core<4>(w4, bufB, (wid & 3) * 16, (wid >> 2) * 4, lane, e);
    int o1 = (wid & 3) * 16 + (lane >> 2), o2 = o1 + 8;
    float b41 = pw4b[o1], b42 = pw4b[o2], t41 = beta2[o1], t42 = beta2[o2];
    float* op1 = out + (size_t)(n * CN + o1) * HW + p0;
    float* op2 = out + (size_t)(n * CN + o2) * HW + p0;
    #pragma unroll
    for (int nt = 0; nt < 4; nt++) {
        int px = (wid >> 2) * 32 + nt * 8 + (lane & 3) * 2;
        float2 r1v, r2v;
        r1v.x = x1s[px * 66 + o1]       + t41 * (e[nt*4+0] + b41);
        r1v.y = x1s[(px + 1) * 66 + o1] + t41 * (e[nt*4+1] + b41);
        r2v.x = x1s[px * 66 + o2]       + t42 * (e[nt*4+2] + b42);
        r2v.y = x1s[(px + 1) * 66 + o2] + t42 * (e[nt*4+3] + b42);
        *(float2*)(op1 + px) = r1v;
        *(float2*)(op2 + px) = r2v;
    }
}

// ---------------- host ------------------------------------------------------------
extern "C" void kernel_launch(void* const* d_in, const int* in_sizes, int n_in,
                              void* d_out, int out_size) {
    const float* x     = (const float*)d_in[0];
    const float* ln1w  = (const float*)d_in[1];
    const float* ln1b  = (const float*)d_in[2];
    const float* pw1w  = (const float*)d_in[3];
    const float* pw1b  = (const float*)d_in[4];
    const float* dww   = (const float*)d_in[5];
    const float* dwb   = (const float*)d_in[6];
    const float* scaw  = (const float*)d_in[7];
    const float* scab  = (const float*)d_in[8];
    const float* pw2w  = (const float*)d_in[9];
    const float* pw2b  = (const float*)d_in[10];
    const float* ln2w  = (const float*)d_in[11];
    const float* ln2b  = (const float*)d_in[12];
    const float* pw3w  = (const float*)d_in[13];
    const float* pw3b  = (const float*)d_in[14];
    const float* pw4w  = (const float*)d_in[15];
    const float* pw4b  = (const float*)d_in[16];
    const float* beta1 = (const float*)d_in[17];
    const float* beta2 = (const float*)d_in[18];

    cudaFuncSetAttribute(k_final, cudaFuncAttributeMaxDynamicSharedMemorySize, 80 * 1024);

    k_stats1<<<NB * CN, 512>>>(x);
    k_prep1<<<NB, C2>>>(ln1w, ln1b, pw1w, pw1b);
    k_pw1<<<dim3(512, NB), 512>>>(x);
    k_dwgate<<<dim3(NB * CN, 8), 256>>>(dww, dwb);
    k_sca<<<NB, CN>>>(scaw, scab, pw2w);
    k_pw2<<<dim3(512, NB), 512>>>(x, pw2b, beta1);
    k_prep3<<<NB, C2>>>(ln2w, ln2b, pw3w, pw3b, pw4w);
    k_final<<<dim3(512, NB), 512, 80 * 1024>>>(pw4b, beta2, (float*)d_out);
}

// round 16
// speedup vs baseline: 1.3388x; 1.1263x over previous
#include <cuda_runtime.h>
#include <cuda_bf16.h>
#include <cstdint>

#define HW 65536
#define CN 64
#define C2 128
#define NB 8
#define EPSV 1e-6f

__device__ unsigned short g_u[(size_t)NB*C2*HW];   // bf16 pw1 output, 134MB
__device__ unsigned short g_g[(size_t)NB*CN*HW];   // bf16 gated, 67MB
__device__ float g_x1[(size_t)NB*CN*HW];           // fp32 first residual, 134MB
__device__ float g_mean1[NB*CN], g_rstd1[NB*CN], g_pool[NB*CN], g_sum2[NB*CN], g_sumsq2[NB*CN];
__device__ float g_b1e[NB*C2], g_b3e[NB*C2];
__device__ __align__(16) unsigned g_w1p[NB*C2*32];
__device__ __align__(16) unsigned g_w2p[NB*CN*32];
__device__ __align__(16) unsigned g_w3p[NB*C2*32];
__device__ __align__(16) unsigned g_w4p[CN*32];

// res = {lo: a, hi: b}
#define CVT2(res,a,b) asm("cvt.rn.satfinite.bf16x2.f32 %0, %1, %2;" : "=r"(res) : "f"(b), "f"(a))
#define BF2F(u) __bfloat162float(__ushort_as_bfloat16(u))

__device__ __forceinline__ void mma16816(float* d, const unsigned* a, unsigned b0, unsigned b1) {
    asm volatile("mma.sync.aligned.m16n8k16.row.col.f32.bf16.bf16.f32 "
        "{%0,%1,%2,%3}, {%4,%5,%6,%7}, {%8,%9}, {%0,%1,%2,%3};"
        : "+f"(d[0]), "+f"(d[1]), "+f"(d[2]), "+f"(d[3])
        : "r"(a[0]), "r"(a[1]), "r"(a[2]), "r"(a[3]), "r"(b0), "r"(b1));
}

// 512-thread staging: fp32 ch-major -> bf16 [128px][36 words]
__device__ __forceinline__ void stage_acts_f32(unsigned* sa, const float* src, int n, int p0,
                                               int lane, int wid) {
    const float4* xa = (const float4*)(src + ((size_t)(n * CN + 2 * lane)) * HW) + (p0 >> 2);
    const float4* xb = xa + (HW >> 2);
    #pragma unroll
    for (int j = 0; j < 2; j++) {
        int px4 = wid * 2 + j;
        float4 a = xa[px4], b = xb[px4];
        int p = px4 * 4;
        unsigned v0, v1, v2, v3;
        CVT2(v0, a.x, b.x); CVT2(v1, a.y, b.y); CVT2(v2, a.z, b.z); CVT2(v3, a.w, b.w);
        sa[(p + 0) * 36 + lane] = v0;
        sa[(p + 1) * 36 + lane] = v1;
        sa[(p + 2) * 36 + lane] = v2;
        sa[(p + 3) * 36 + lane] = v3;
    }
}

__device__ __forceinline__ void stage_acts_bf16(unsigned* sa, const unsigned short* src,
                                                int n, int p0, int lane, int wid) {
    const ushort4* ga = (const ushort4*)(src + ((size_t)(n * CN + 2 * lane)) * HW + p0);
    const ushort4* gb = ga + (HW >> 2);
    #pragma unroll
    for (int j = 0; j < 2; j++) {
        int px4 = wid * 2 + j;
        ushort4 a = ga[px4], b = gb[px4];
        int p = px4 * 4;
        sa[(p + 0) * 36 + lane] = (unsigned)a.x | ((unsigned)b.x << 16);
        sa[(p + 1) * 36 + lane] = (unsigned)a.y | ((unsigned)b.y << 16);
        sa[(p + 2) * 36 + lane] = (unsigned)a.z | ((unsigned)b.z << 16);
        sa[(p + 3) * 36 + lane] = (unsigned)a.w | ((unsigned)b.w << 16);
    }
}

// 512-thread weight copy
__device__ __forceinline__ void copy_w(unsigned* sw, const unsigned* gw, int rows, int t) {
    int r = t >> 5, w = t & 31;
    for (; r < rows; r += 16) sw[r * 36 + w] = gw[r * 32 + w];
}

// single-strip warp GEMM (R13)
template<int NT>
__device__ __forceinline__ void gemm_core(const unsigned* sw, const unsigned* sa,
                                          int ms, int ntb, int lane, float* d) {
    int r = ms + (lane >> 2), kp = lane & 3;
    #pragma unroll
    for (int ks = 0; ks < 4; ks++) {
        unsigned a[4];
        a[0] = sw[r * 36 + ks * 8 + kp];
        a[1] = sw[(r + 8) * 36 + ks * 8 + kp];
        a[2] = sw[r * 36 + ks * 8 + kp + 4];
        a[3] = sw[(r + 8) * 36 + ks * 8 + kp + 4];
        #pragma unroll
        for (int nt = 0; nt < NT; nt++) {
            int px = (ntb + nt) * 8 + (lane >> 2);
            unsigned b0 = sa[px * 36 + ks * 8 + kp];
            unsigned b1 = sa[px * 36 + ks * 8 + kp + 4];
            mma16816(d + nt * 4, a, b0, b1);
        }
    }
}

// paired-strip warp GEMM: rows (ms..ms+15) -> d[0..4NT), rows (ms+64..ms+79) -> d[16..16+4NT)
// B fragments shared by both strips.
template<int NT>
__device__ __forceinline__ void gemm_core2(const unsigned* sw, const unsigned* sa,
                                           int ms, int ntb, int lane, float* d) {
    int r = ms + (lane >> 2), kp = lane & 3;
    #pragma unroll
    for (int ks = 0; ks < 4; ks++) {
        unsigned a0[4], a1[4];
        a0[0] = sw[r * 36 + ks * 8 + kp];
        a0[1] = sw[(r + 8) * 36 + ks * 8 + kp];
        a0[2] = sw[r * 36 + ks * 8 + kp + 4];
        a0[3] = sw[(r + 8) * 36 + ks * 8 + kp + 4];
        a1[0] = sw[(r + 64) * 36 + ks * 8 + kp];
        a1[1] = sw[(r + 72) * 36 + ks * 8 + kp];
        a1[2] = sw[(r + 64) * 36 + ks * 8 + kp + 4];
        a1[3] = sw[(r + 72) * 36 + ks * 8 + kp + 4];
        #pragma unroll
        for (int nt = 0; nt < NT; nt++) {
            int px = (ntb + nt) * 8 + (lane >> 2);
            unsigned b0 = sa[px * 36 + ks * 8 + kp];
            unsigned b1 = sa[px * 36 + ks * 8 + kp + 4];
            mma16816(d + nt * 4, a0, b0, b1);
            mma16816(d + 16 + nt * 4, a1, b0, b1);
        }
    }
}

// ---------------- K1: LN1 stats ---------------------------------------------------
__global__ void __launch_bounds__(512) k_stats1(const float* __restrict__ x) {
    int nc = blockIdx.x;
    const float4* p = (const float4*)(x + (size_t)nc * HW);
    float s = 0.f, q = 0.f;
    for (int j = threadIdx.x; j < HW / 4; j += 512) {
        float4 v = p[j];
        s += v.x + v.y + v.z + v.w;
        q += v.x * v.x + v.y * v.y + v.z * v.z + v.w * v.w;
    }
    __shared__ float rs[16], rq[16];
    for (int o = 16; o; o >>= 1) {
        s += __shfl_down_sync(0xffffffffu, s, o);
        q += __shfl_down_sync(0xffffffffu, q, o);
    }
    if ((threadIdx.x & 31) == 0) { rs[threadIdx.x >> 5] = s; rq[threadIdx.x >> 5] = q; }
    __syncthreads();
    if (threadIdx.x == 0) {
        float S = 0.f, Q = 0.f;
        for (int i = 0; i < 16; i++) { S += rs[i]; Q += rq[i]; }
        float m = S * (1.f / HW);
        g_mean1[nc] = m;
        g_rstd1[nc] = rsqrtf(Q * (1.f / HW) - m * m + EPSV);
    }
}

// ---------------- K2: fold LN1 -> pw1 packed bf16 ---------------------------------
__global__ void k_prep1(const float* __restrict__ ln1w, const float* __restrict__ ln1b,
                        const float* __restrict__ pw1w, const float* __restrict__ pw1b) {
    int n = blockIdx.x, o = threadIdx.x;   // 128
    float bias = pw1b[o], row[CN];
    for (int i = 0; i < CN; i++) {
        float a  = g_rstd1[n * CN + i] * ln1w[i];
        float c0 = ln1b[i] - g_mean1[n * CN + i] * a;
        float w  = pw1w[o * CN + i];
        bias += w * c0;
        row[i] = w * a;
    }
    g_b1e[n * C2 + o] = bias;
    unsigned* dst = g_w1p + (n * C2 + o) * 32;
    for (int j = 0; j < 32; j++) { unsigned pk; CVT2(pk, row[2*j], row[2*j+1]); dst[j] = pk; }
    int idx = n * C2 + o;
    if (idx < NB * CN) { g_pool[idx] = 0.f; g_sum2[idx] = 0.f; g_sumsq2[idx] = 0.f; }
}

// ---------------- K3: pw1 mma GEMM (512 thr, 128px, paired strips) ----------------
__global__ void __launch_bounds__(512) k_pw1(const float* __restrict__ x) {
    __shared__ __align__(16) unsigned sw[C2 * 36];
    __shared__ __align__(16) unsigned sa[128 * 36];
    int t = threadIdx.x, wid = t >> 5, lane = t & 31;
    int n = blockIdx.y, p0 = blockIdx.x * 128;
    copy_w(sw, g_w1p + n * C2 * 32, C2, t);
    stage_acts_f32(sa, x, n, p0, lane, wid);
    __syncthreads();
    float d[32];
    #pragma unroll
    for (int i = 0; i < 32; i++) d[i] = 0.f;
    gemm_core2<4>(sw, sa, (wid & 3) * 16, (wid >> 2) * 4, lane, d);
    int o1 = (wid & 3) * 16 + (lane >> 2), o2 = o1 + 8, o3 = o1 + 64, o4 = o1 + 72;
    float bi1 = g_b1e[n * C2 + o1], bi2 = g_b1e[n * C2 + o2];
    float bi3 = g_b1e[n * C2 + o3], bi4 = g_b1e[n * C2 + o4];
    unsigned short* u1 = g_u + (size_t)(n * C2 + o1) * HW + p0;
    unsigned short* u2 = g_u + (size_t)(n * C2 + o2) * HW + p0;
    unsigned short* u3 = g_u + (size_t)(n * C2 + o3) * HW + p0;
    unsigned short* u4 = g_u + (size_t)(n * C2 + o4) * HW + p0;
    #pragma unroll
    for (int nt = 0; nt < 4; nt++) {
        int px = (wid >> 2) * 32 + nt * 8 + (lane & 3) * 2;
        unsigned pk1, pk2, pk3, pk4;
        CVT2(pk1, d[nt*4+0] + bi1, d[nt*4+1] + bi1);
        CVT2(pk2, d[nt*4+2] + bi2, d[nt*4+3] + bi2);
        CVT2(pk3, d[16+nt*4+0] + bi3, d[16+nt*4+1] + bi3);
        CVT2(pk4, d[16+nt*4+2] + bi4, d[16+nt*4+3] + bi4);
        *(unsigned*)(u1 + px) = pk1;
        *(unsigned*)(u2 + px) = pk2;
        *(unsigned*)(u3 + px) = pk3;
        *(unsigned*)(u4 + px) = pk4;
    }
}

// ---------------- K4: depthwise 3x3 + gate + pool (register-tiled 4x4) ------------
__global__ void __launch_bounds__(256) k_dwgate(const float* __restrict__ dww,
                                                const float* __restrict__ dwb) {
    __shared__ float s[2][18][256];
    __shared__ float red[8];
    int t = threadIdx.x, tx = t & 63, ty = t >> 6;
    int nc = blockIdx.x, n = nc >> 6, c = nc & 63;
    int strip0 = blockIdx.y * 32;
    const unsigned short* u0 = g_u + ((size_t)(n * C2 + c)) * HW;
    const unsigned short* u1 = g_u + ((size_t)(n * C2 + c + 64)) * HW;
    unsigned short* gp = g_g + ((size_t)(n * CN + c)) * HW;
    float w0[9], w1[9];
    #pragma unroll
    for (int k = 0; k < 9; k++) { w0[k] = __ldg(dww + c * 9 + k); w1[k] = __ldg(dww + (c + 64) * 9 + k); }
    float b0 = __ldg(dwb + c), b1 = __ldg(dwb + c + 64);
    float psum = 0.f;
    #pragma unroll 1
    for (int it = 0; it < 2; it++) {
        int base = strip0 + it * 16;
        #pragma unroll
        for (int k = 0; k < 9; k++) {
            int idx = t + k * 256;
            int ch = (idx >= 1152);
            int rem = idx - ch * 1152;
            int lr = rem >> 6, c8 = rem & 63;
            int ar = base - 1 + lr;
            float4 f = make_float4(0.f, 0.f, 0.f, 0.f);
            if ((unsigned)ar < 256u) {
                ushort4 v = *(const ushort4*)((ch ? u1 : u0) + ar * 256 + c8 * 4);
                f = make_float4(BF2F(v.x), BF2F(v.y), BF2F(v.z), BF2F(v.w));
            }
            *(float4*)(&s[ch][lr][c8 * 4]) = f;
        }
        __syncthreads();
        float acc0[16], acc1[16];
        #pragma unroll
        for (int i = 0; i < 16; i++) { acc0[i] = b0; acc1[i] = b1; }
        #pragma unroll
        for (int ch = 0; ch < 2; ch++) {
            float* acc = ch ? acc1 : acc0;
            const float* w = ch ? w1 : w0;
            #pragma unroll
            for (int lr = 0; lr < 6; lr++) {
                const float* row = &s[ch][ty * 4 + lr][0];
                float4 cv = *(const float4*)(row + tx * 4);
                float i0 = tx ? row[tx * 4 - 1] : 0.f;
                float i5 = (tx != 63) ? row[tx * 4 + 4] : 0.f;
                float i1 = cv.x, i2 = cv.y, i3 = cv.z, i4 = cv.w;
                #pragma unroll
                for (int ky = 0; ky < 3; ky++) {
                    int q = lr - ky;
                    if (q >= 0 && q < 4) {
                        acc[q*4+0] += w[ky*3]*i0 + w[ky*3+1]*i1 + w[ky*3+2]*i2;
                        acc[q*4+1] += w[ky*3]*i1 + w[ky*3+1]*i2 + w[ky*3+2]*i3;
                        acc[q*4+2] += w[ky*3]*i2 + w[ky*3+1]*i3 + w[ky*3+2]*i4;
                        acc[q*4+3] += w[ky*3]*i3 + w[ky*3+1]*i4 + w[ky*3+2]*i5;
                    }
                }
            }
        }
        #pragma unroll
        for (int q = 0; q < 4; q++) {
            int r = base + ty * 4 + q;
            float g0 = acc0[q*4+0] * acc1[q*4+0];
            float g1 = acc0[q*4+1] * acc1[q*4+1];
            float g2 = acc0[q*4+2] * acc1[q*4+2];
            float g3 = acc0[q*4+3] * acc1[q*4+3];
            unsigned pk0, pk1;
            CVT2(pk0, g0, g1); CVT2(pk1, g2, g3);
            *(uint2*)(gp + r * 256 + tx * 4) = make_uint2(pk0, pk1);
            psum += (g0 + g1) + (g2 + g3);
        }
        __syncthreads();
    }
    for (int o = 16; o; o >>= 1) psum += __shfl_down_sync(0xffffffffu, psum, o);
    if ((t & 31) == 0) red[t >> 5] = psum;
    __syncthreads();
    if (t < 8) {
        float v = red[t];
        v += __shfl_down_sync(0xffu, v, 4);
        v += __shfl_down_sync(0xffu, v, 2);
        v += __shfl_down_sync(0xffu, v, 1);
        if (t == 0) atomicAdd(&g_pool[nc], v);
    }
}

// ---------------- K5: SCA -> pw2 packed bf16 --------------------------------------
__global__ void k_sca(const float* __restrict__ scaw, const float* __restrict__ scab,
                      const float* __restrict__ pw2w) {
    int n = blockIdx.x, o = threadIdx.x;   // 64
    __shared__ float pm[CN], sc[CN];
    pm[o] = g_pool[n * CN + o] * (1.f / HW);
    __syncthreads();
    float acc = scab[o];
    for (int i = 0; i < CN; i++) acc += scaw[o * CN + i] * pm[i];
    sc[o] = 1.f / (1.f + expf(-acc));
    __syncthreads();
    unsigned* dst = g_w2p + (n * CN + o) * 32;
    for (int j = 0; j < 32; j++) {
        unsigned pk;
        CVT2(pk, pw2w[o * CN + 2*j] * sc[2*j], pw2w[o * CN + 2*j+1] * sc[2*j+1]);
        dst[j] = pk;
    }
}

// ---------------- K6: pw2 mma GEMM + residual + LN2 stats (512 thr, 128px) --------
__global__ void __launch_bounds__(512) k_pw2(const float* __restrict__ x,
                                             const float* __restrict__ pw2b,
                                             const float* __restrict__ beta1) {
    __shared__ __align__(16) unsigned sw[CN * 36];
    __shared__ __align__(16) unsigned sa[128 * 36];
    int t = threadIdx.x, wid = t >> 5, lane = t & 31;
    int n = blockIdx.y, p0 = blockIdx.x * 128;
    copy_w(sw, g_w2p + n * CN * 32, CN, t);
    stage_acts_bf16(sa, g_g, n, p0, lane, wid);
    __syncthreads();
    float d[16];
    #pragma unroll
    for (int i = 0; i < 16; i++) d[i] = 0.f;
    gemm_core<4>(sw, sa, (wid & 3) * 16, (wid >> 2) * 4, lane, d);
    int o1 = (wid & 3) * 16 + (lane >> 2), o2 = o1 + 8;
    float b1 = pw2b[o1], b2 = pw2b[o2], t1 = beta1[o1], t2 = beta1[o2];
    size_t off1 = (size_t)(n * CN + o1) * HW + p0;
    size_t off2 = (size_t)(n * CN + o2) * HW + p0;
    float s1 = 0.f, q1 = 0.f, s2 = 0.f, q2 = 0.f;
    #pragma unroll
    for (int nt = 0; nt < 4; nt++) {
        int px = (wid >> 2) * 32 + nt * 8 + (lane & 3) * 2;
        float2 xv1 = *(const float2*)(x + off1 + px);
        float2 xv2 = *(const float2*)(x + off2 + px);
        float2 r1 = make_float2(xv1.x + t1 * (d[nt*4+0] + b1), xv1.y + t1 * (d[nt*4+1] + b1));
        float2 r2 = make_float2(xv2.x + t2 * (d[nt*4+2] + b2), xv2.y + t2 * (d[nt*4+3] + b2));
        *(float2*)(g_x1 + off1 + px) = r1;
        *(float2*)(g_x1 + off2 + px) = r2;
        s1 += r1.x + r1.y; q1 += r1.x * r1.x + r1.y * r1.y;
        s2 += r2.x + r2.y; q2 += r2.x * r2.x + r2.y * r2.y;
    }
    s1 += __shfl_xor_sync(~0u, s1, 1); s1 += __shfl_xor_sync(~0u, s1, 2);
    q1 += __shfl_xor_sync(~0u, q1, 1); q1 += __shfl_xor_sync(~0u, q1, 2);
    s2 += __shfl_xor_sync(~0u, s2, 1); s2 += __shfl_xor_sync(~0u, s2, 2);
    q2 += __shfl_xor_sync(~0u, q2, 1); q2 += __shfl_xor_sync(~0u, q2, 2);
    if ((lane & 3) == 0) {
        atomicAdd(&g_sum2[n * CN + o1], s1);
        atomicAdd(&g_sumsq2[n * CN + o1], q1);
        atomicAdd(&g_sum2[n * CN + o2], s2);
        atomicAdd(&g_sumsq2[n * CN + o2], q2);
    }
}

// ---------------- K7: LN2 -> pw3 packed; pw4 packed -------------------------------
__global__ void k_prep3(const float* __restrict__ ln2w, const float* __restrict__ ln2b,
                        const float* __restrict__ pw3w, const float* __restrict__ pw3b,
                        const float* __restrict__ pw4w) {
    int n = blockIdx.x, o = threadIdx.x;   // 128
    __shared__ float m2[CN], r2[CN];
    if (o < CN) {
        float m = g_sum2[n * CN + o] * (1.f / HW);
        m2[o] = m;
        r2[o] = rsqrtf(g_sumsq2[n * CN + o] * (1.f / HW) - m * m + EPSV);
    }
    __syncthreads();
    float bias = pw3b[o], row[CN];
    for (int i = 0; i < CN; i++) {
        float a  = r2[i] * ln2w[i];
        float c0 = ln2b[i] - m2[i] * a;
        float w  = pw3w[o * CN + i];
        bias += w * c0;
        row[i] = w * a;
    }
    g_b3e[n * C2 + o] = bias;
    unsigned* dst = g_w3p + (n * C2 + o) * 32;
    for (int j = 0; j < 32; j++) { unsigned pk; CVT2(pk, row[2*j], row[2*j+1]); dst[j] = pk; }
    if (n == 0 && o < CN) {
        unsigned* d4 = g_w4p + o * 32;
        for (int j = 0; j < 32; j++) {
            unsigned pk; CVT2(pk, pw4w[o * CN + 2*j], pw4w[o * CN + 2*j+1]);
            d4[j] = pk;
        }
    }
}

// ---------------- K8: pw3 paired MMA -> register gate -> pw4 MMA -> out -----------
__global__ void __launch_bounds__(512) k_final(const float* __restrict__ pw4b,
                                               const float* __restrict__ beta2,
                                               float* __restrict__ out) {
    extern __shared__ __align__(16) char smem[];
    float*    x1s  = (float*)smem;                              // [128][66] fp32 = 33792
    unsigned* w3   = (unsigned*)(smem + 33792);                 // 18432
    unsigned* w4   = (unsigned*)(smem + 33792 + 18432);         // 9216
    unsigned* bufB = (unsigned*)(smem + 33792 + 18432 + 9216);  // 18432 (B3 then B4)
    int t = threadIdx.x, wid = t >> 5, lane = t & 31;
    int n = blockIdx.y, p0 = blockIdx.x * 128;
    copy_w(w3, g_w3p + n * C2 * 32, C2, t);
    copy_w(w4, g_w4p, CN, t);
    {
        const float4* xa = (const float4*)(g_x1 + ((size_t)(n * CN + 2 * lane)) * HW) + (p0 >> 2);
        const float4* xb = xa + (HW >> 2);
        float2* x1s2 = (float2*)x1s;
        #pragma unroll
        for (int j = 0; j < 2; j++) {
            int px4 = wid * 2 + j;
            float4 a = xa[px4], b = xb[px4];
            int p = px4 * 4;
            x1s2[(p + 0) * 33 + lane] = make_float2(a.x, b.x);
            x1s2[(p + 1) * 33 + lane] = make_float2(a.y, b.y);
            x1s2[(p + 2) * 33 + lane] = make_float2(a.z, b.z);
            x1s2[(p + 3) * 33 + lane] = make_float2(a.w, b.w);
            unsigned v0, v1, v2, v3;
            CVT2(v0, a.x, b.x); CVT2(v1, a.y, b.y); CVT2(v2, a.z, b.z); CVT2(v3, a.w, b.w);
            bufB[(p + 0) * 36 + lane] = v0;
            bufB[(p + 1) * 36 + lane] = v1;
            bufB[(p + 2) * 36 + lane] = v2;
            bufB[(p + 3) * 36 + lane] = v3;
        }
    }
    __syncthreads();
    // pw3: paired strips (c, c+64) -> gate operands live in the same thread
    float d[32];
    #pragma unroll
    for (int i = 0; i < 32; i++) d[i] = 0.f;
    gemm_core2<4>(w3, bufB, (wid & 3) * 16, (wid >> 2) * 4, lane, d);
    int r1 = (wid & 3) * 16 + (lane >> 2), r2 = r1 + 8;
    float b31 = g_b3e[n * C2 + r1], b32 = g_b3e[n * C2 + r2];
    float b33 = g_b3e[n * C2 + r1 + 64], b34 = g_b3e[n * C2 + r2 + 64];
    __syncthreads();   // all warps done reading bufB (B3)
    {   // register gate -> write B4 bf16 into bufB [px][72]
        unsigned short* b4s = (unsigned short*)bufB;
        #pragma unroll
        for (int nt = 0; nt < 4; nt++) {
            int px = (wid >> 2) * 32 + nt * 8 + (lane & 3) * 2;
            float g0 = (d[nt*4+0] + b31) * (d[16+nt*4+0] + b33);
            float g1 = (d[nt*4+1] + b31) * (d[16+nt*4+1] + b33);
            float g2 = (d[nt*4+2] + b32) * (d[16+nt*4+2] + b34);
            float g3 = (d[nt*4+3] + b32) * (d[16+nt*4+3] + b34);
            b4s[px * 72 + r1]       = __bfloat16_as_ushort(__float2bfloat16_rn(g0));
            b4s[(px + 1) * 72 + r1] = __bfloat16_as_ushort(__float2bfloat16_rn(g1));
            b4s[px * 72 + r2]       = __bfloat16_as_ushort(__float2bfloat16_rn(g2));
            b4s[(px + 1) * 72 + r2] = __bfloat16_as_ushort(__float2bfloat16_rn(g3));
        }
    }
    __syncthreads();
    float e[16];
    #pragma unroll
    for (int i = 0; i < 16; i++) e[i] = 0.f;
    gemm_core<4>(w4, bufB, (wid & 3) * 16, (wid >> 2) * 4, lane, e);
    int o1 = (wid & 3) * 16 + (lane >> 2), o2 = o1 + 8;
    float b41 = pw4b[o1], b42 = pw4b[o2], t41 = beta2[o1], t42 = beta2[o2];
    float* op1 = out + (size_t)(n * CN + o1) * HW + p0;
    float* op2 = out + (size_t)(n * CN + o2) * HW + p0;
    #pragma unroll
    for (int nt = 0; nt < 4; nt++) {
        int px = (wid >> 2) * 32 + nt * 8 + (lane & 3) * 2;
        float2 r1v, r2v;
        r1v.x = x1s[px * 66 + o1]       + t41 * (e[nt*4+0] + b41);
        r1v.y = x1s[(px + 1) * 66 + o1] + t41 * (e[nt*4+1] + b41);
        r2v.x = x1s[px * 66 + o2]       + t42 * (e[nt*4+2] + b42);
        r2v.y = x1s[(px + 1) * 66 + o2] + t42 * (e[nt*4+3] + b42);
        *(float2*)(op1 + px) = r1v;
        *(float2*)(op2 + px) = r2v;
    }
}

// ---------------- host ------------------------------------------------------------
extern "C" void kernel_launch(void* const* d_in, const int* in_sizes, int n_in,
                              void* d_out, int out_size) {
    const float* x     = (const float*)d_in[0];
    const float* ln1w  = (const float*)d_in[1];
    const float* ln1b  = (const float*)d_in[2];
    const float* pw1w  = (const float*)d_in[3];
    const float* pw1b  = (const float*)d_in[4];
    const float* dww   = (const float*)d_in[5];
    const float* dwb   = (const float*)d_in[6];
    const float* scaw  = (const float*)d_in[7];
    const float* scab  = (const float*)d_in[8];
    const float* pw2w  = (const float*)d_in[9];
    const float* pw2b  = (const float*)d_in[10];
    const float* ln2w  = (const float*)d_in[11];
    const float* ln2b  = (const float*)d_in[12];
    const float* pw3w  = (const float*)d_in[13];
    const float* pw3b  = (const float*)d_in[14];
    const float* pw4w  = (const float*)d_in[15];
    const float* pw4b  = (const float*)d_in[16];
    const float* beta1 = (const float*)d_in[17];
    const float* beta2 = (const float*)d_in[18];

    cudaFuncSetAttribute(k_final, cudaFuncAttributeMaxDynamicSharedMemorySize, 80 * 1024);

    k_stats1<<<NB * CN, 512>>>(x);
    k_prep1<<<NB, C2>>>(ln1w, ln1b, pw1w, pw1b);
    k_pw1<<<dim3(512, NB), 512>>>(x);
    k_dwgate<<<dim3(NB * CN, 8), 256>>>(dww, dwb);
    k_sca<<<NB, CN>>>(scaw, scab, pw2w);
    k_pw2<<<dim3(512, NB), 512>>>(x, pw2b, beta1);
    k_prep3<<<NB, C2>>>(ln2w, ln2b, pw3w, pw3b, pw4w);
    k_final<<<dim3(512, NB), 512, 80 * 1024>>>(pw4b, beta2, (float*)d_out);
}